// round 1
// baseline (speedup 1.0000x reference)
#include <cuda_runtime.h>

// ---------------------------------------------------------------------------
// Problem constants
// ---------------------------------------------------------------------------
#define NB      32          // batch
#define P1      25
#define P2      24
#define S       600         // P1*P2 tokens per batch
#define D1      8
#define D2      8
#define D3      12
#define C       768         // D1*D2*D3
#define NHEADS  16          // H1*H2*H3 = 2*2*4
#define HD      48          // X*Y*Z = 4*4*3
#define NTOK    (NB * S)    // 19200
#define QKV_ELEMS (NB * NHEADS * S * HD)   // 14,745,600

// scale = 1/sqrt(48); fold log2(e) so softmax runs in base-2 domain
#define CSCALE  (0.14433756729740643f * 1.4426950408889634f)

// ---------------------------------------------------------------------------
// Scratch (static device globals; no allocations allowed)
// ---------------------------------------------------------------------------
__device__ float g_Q[QKV_ELEMS];
__device__ float g_K[QKV_ELEMS];
__device__ float g_V[QKV_ELEMS];
__device__ float g_O[QKV_ELEMS];

// ---------------------------------------------------------------------------
// Fused TLE for q,k,v:  per token, 3-mode contraction + scatter to head layout
//   channel (a,c,d): a = x*2+h1, c = y*2+h2, d = z*4+h3
//   head  h = h1*8 + h2*4 + h3 ;  dpos = x*12 + y*3 + z
//   Q layout: [b][h][s][dpos]  (head-contiguous rows of 48)
// ---------------------------------------------------------------------------
__global__ void __launch_bounds__(256) tle_qkv_kernel(
    const float* __restrict__ x,
    const float* __restrict__ wq1, const float* __restrict__ wq2,
    const float* __restrict__ wq3, const float* __restrict__ bq,
    const float* __restrict__ wk1, const float* __restrict__ wk2,
    const float* __restrict__ wk3, const float* __restrict__ bk,
    const float* __restrict__ wv1, const float* __restrict__ wv2,
    const float* __restrict__ wv3, const float* __restrict__ bv)
{
    __shared__ float xs[C];
    __shared__ float t1[C];
    __shared__ float t2[C];
    __shared__ float w1s[64];
    __shared__ float w2s[64];
    __shared__ float w3s[144];

    const int tok = blockIdx.x;
    const int tid = threadIdx.x;
    const int b   = tok / S;
    const int s   = tok % S;

    const float* xp = x + (size_t)tok * C;
    for (int t = tid; t < C; t += 256) xs[t] = xp[t];

    const float* W1[3] = {wq1, wk1, wv1};
    const float* W2[3] = {wq2, wk2, wv2};
    const float* W3[3] = {wq3, wk3, wv3};
    const float* BB[3] = {bq,  bk,  bv };
    float* const OUT[3] = {g_Q, g_K, g_V};

    for (int p = 0; p < 3; ++p) {
        __syncthreads();   // xs ready (p=0); previous projection done reading t2/w3s
        if (tid < 64)                 w1s[tid]       = W1[p][tid];
        else if (tid < 128)           w2s[tid - 64]  = W2[p][tid - 64];
        else if (tid < 272)           w3s[tid - 128] = W3[p][tid - 128];
        __syncthreads();

        // step 1: t1[a][j][k] = sum_i w1[a,i] * x[i][j][k]
        for (int idx = tid; idx < C; idx += 256) {
            const int a = idx / 96, jk = idx % 96;
            float acc = 0.f;
            #pragma unroll
            for (int i = 0; i < 8; ++i) acc += w1s[a * 8 + i] * xs[i * 96 + jk];
            t1[idx] = acc;
        }
        __syncthreads();

        // step 2: t2[a][c][k] = sum_j w2[c,j] * t1[a][j][k]
        for (int idx = tid; idx < C; idx += 256) {
            const int a = idx / 96, r = idx % 96, c2 = r / 12, k = r % 12;
            float acc = 0.f;
            #pragma unroll
            for (int j = 0; j < 8; ++j) acc += w2s[c2 * 8 + j] * t1[a * 96 + j * 12 + k];
            t2[idx] = acc;
        }
        __syncthreads();

        // step 3: out[a][c][d] = sum_k w3[d,k] * t2[a][c][k] + bias ; scatter to head layout
        float* const       outp = OUT[p];
        const float* const bp   = BB[p];
        for (int idx = tid; idx < C; idx += 256) {
            const int a = idx / 96, r = idx % 96, c2 = r / 12, d = r % 12;
            float acc = bp[idx];
            #pragma unroll
            for (int k = 0; k < 12; ++k) acc += w3s[d * 12 + k] * t2[a * 96 + c2 * 12 + k];
            const int h    = (a & 1) * 8 + (c2 & 1) * 4 + (d & 3);
            const int dpos = (a >> 1) * 12 + (c2 >> 1) * 3 + (d >> 2);
            outp[(((size_t)b * NHEADS + h) * S + s) * HD + dpos] = acc;
        }
    }
}

// ---------------------------------------------------------------------------
// Flash-style attention, fp32 SIMT.
//   grid = (ceil(S/128), NB*NHEADS), block = 128. One query row per thread.
//   Online softmax in base-2 domain; lazy accumulator rescale (only on new max).
// ---------------------------------------------------------------------------
#define CHUNK 64

__global__ void __launch_bounds__(128) attn_kernel()
{
    __shared__ float4 ks[CHUNK * 12];
    __shared__ float4 vs[CHUNK * 12];

    const int hid = blockIdx.y;                  // b*16 + head
    const int r   = blockIdx.x * 128 + threadIdx.x;
    const bool valid = (r < S);

    const float4* __restrict__ Qh = (const float4*)(g_Q + (size_t)hid * S * HD);
    const float4* __restrict__ Kh = (const float4*)(g_K + (size_t)hid * S * HD);
    const float4* __restrict__ Vh = (const float4*)(g_V + (size_t)hid * S * HD);
    float4* __restrict__       Oh = (float4*)(g_O + (size_t)hid * S * HD);

    float4 qv[12];
    if (valid) {
        #pragma unroll
        for (int t = 0; t < 12; ++t) {
            float4 v = Qh[r * 12 + t];
            v.x *= CSCALE; v.y *= CSCALE; v.z *= CSCALE; v.w *= CSCALE;
            qv[t] = v;
        }
    }

    float m = -1e30f, l = 0.f;
    float acc[48];
    #pragma unroll
    for (int d = 0; d < 48; ++d) acc[d] = 0.f;

    for (int j0 = 0; j0 < S; j0 += CHUNK) {
        const int cnt = (S - j0 < CHUNK) ? (S - j0) : CHUNK;
        __syncthreads();
        for (int t = threadIdx.x; t < cnt * 12; t += 128) {
            ks[t] = Kh[j0 * 12 + t];
            vs[t] = Vh[j0 * 12 + t];
        }
        __syncthreads();

        if (valid) {
            for (int j = 0; j < cnt; ++j) {
                float sdot = 0.f;
                #pragma unroll
                for (int t = 0; t < 12; ++t) {
                    const float4 k4 = ks[j * 12 + t];
                    sdot += qv[t].x * k4.x + qv[t].y * k4.y
                          + qv[t].z * k4.z + qv[t].w * k4.w;
                }
                if (sdot > m) {
                    const float alpha = exp2f(m - sdot);  // 0 on first hit
                    m = sdot;
                    l *= alpha;
                    #pragma unroll
                    for (int d = 0; d < 48; ++d) acc[d] *= alpha;
                }
                const float p = exp2f(sdot - m);
                l += p;
                #pragma unroll
                for (int t = 0; t < 12; ++t) {
                    const float4 v4 = vs[j * 12 + t];
                    acc[t * 4 + 0] += p * v4.x;
                    acc[t * 4 + 1] += p * v4.y;
                    acc[t * 4 + 2] += p * v4.z;
                    acc[t * 4 + 3] += p * v4.w;
                }
            }
        }
    }

    if (valid) {
        const float inv = 1.0f / l;
        #pragma unroll
        for (int t = 0; t < 12; ++t) {
            float4 o4;
            o4.x = acc[t * 4 + 0] * inv;
            o4.y = acc[t * 4 + 1] * inv;
            o4.z = acc[t * 4 + 2] * inv;
            o4.w = acc[t * 4 + 3] * inv;
            Oh[r * 12 + t] = o4;
        }
    }
}

// ---------------------------------------------------------------------------
// Output TLE: gather heads back to (a,c,d) channels, 3-mode contraction, store
// ---------------------------------------------------------------------------
__global__ void __launch_bounds__(256) tle_o_kernel(
    const float* __restrict__ wo1, const float* __restrict__ wo2,
    const float* __restrict__ wo3, const float* __restrict__ bo,
    float* __restrict__ out)
{
    __shared__ float xs[C];
    __shared__ float t1[C];
    __shared__ float t2[C];
    __shared__ float w1s[64];
    __shared__ float w2s[64];
    __shared__ float w3s[144];

    const int tok = blockIdx.x;
    const int tid = threadIdx.x;
    const int b   = tok / S;
    const int s   = tok % S;

    // gather: channel (a,c,d) <- g_O[b][h][s][dpos]   (merge_heads)
    for (int idx = tid; idx < C; idx += 256) {
        const int a = idx / 96, r = idx % 96, c2 = r / 12, d = r % 12;
        const int h    = (a & 1) * 8 + (c2 & 1) * 4 + (d & 3);
        const int dpos = (a >> 1) * 12 + (c2 >> 1) * 3 + (d >> 2);
        xs[idx] = g_O[(((size_t)b * NHEADS + h) * S + s) * HD + dpos];
    }
    if (tid < 64)            w1s[tid]       = wo1[tid];
    else if (tid < 128)      w2s[tid - 64]  = wo2[tid - 64];
    else if (tid < 272)      w3s[tid - 128] = wo3[tid - 128];
    __syncthreads();

    for (int idx = tid; idx < C; idx += 256) {
        const int a = idx / 96, jk = idx % 96;
        float acc = 0.f;
        #pragma unroll
        for (int i = 0; i < 8; ++i) acc += w1s[a * 8 + i] * xs[i * 96 + jk];
        t1[idx] = acc;
    }
    __syncthreads();

    for (int idx = tid; idx < C; idx += 256) {
        const int a = idx / 96, r = idx % 96, c2 = r / 12, k = r % 12;
        float acc = 0.f;
        #pragma unroll
        for (int j = 0; j < 8; ++j) acc += w2s[c2 * 8 + j] * t1[a * 96 + j * 12 + k];
        t2[idx] = acc;
    }
    __syncthreads();

    float* const op = out + (size_t)tok * C;
    for (int idx = tid; idx < C; idx += 256) {
        const int a = idx / 96, r = idx % 96, c2 = r / 12, d = r % 12;
        float acc = bo[idx];
        #pragma unroll
        for (int k = 0; k < 12; ++k) acc += w3s[d * 12 + k] * t2[a * 96 + c2 * 12 + k];
        op[idx] = acc;
    }
}

// ---------------------------------------------------------------------------
// Launch
// ---------------------------------------------------------------------------
extern "C" void kernel_launch(void* const* d_in, const int* in_sizes, int n_in,
                              void* d_out, int out_size)
{
    const float* x   = (const float*)d_in[0];
    const float* wq1 = (const float*)d_in[1];
    const float* wq2 = (const float*)d_in[2];
    const float* wq3 = (const float*)d_in[3];
    const float* bq  = (const float*)d_in[4];
    const float* wk1 = (const float*)d_in[5];
    const float* wk2 = (const float*)d_in[6];
    const float* wk3 = (const float*)d_in[7];
    const float* bk  = (const float*)d_in[8];
    const float* wv1 = (const float*)d_in[9];
    const float* wv2 = (const float*)d_in[10];
    const float* wv3 = (const float*)d_in[11];
    const float* bv  = (const float*)d_in[12];
    const float* wo1 = (const float*)d_in[13];
    const float* wo2 = (const float*)d_in[14];
    const float* wo3 = (const float*)d_in[15];
    const float* bo  = (const float*)d_in[16];
    float* out = (float*)d_out;

    tle_qkv_kernel<<<NTOK, 256>>>(x, wq1, wq2, wq3, bq,
                                     wk1, wk2, wk3, bk,
                                     wv1, wv2, wv3, bv);

    dim3 agrid((S + 127) / 128, NB * NHEADS);
    attn_kernel<<<agrid, 128>>>();

    tle_o_kernel<<<NTOK, 256>>>(wo1, wo2, wo3, bo, out);
}

// round 3
// speedup vs baseline: 2.4172x; 2.4172x over previous
#include <cuda_runtime.h>
#include <cstdint>

// ---------------------------------------------------------------------------
// Problem constants
// ---------------------------------------------------------------------------
#define NB      32
#define S       600
#define C       768
#define HD      48
#define NHEADS  16
#define NBH     (NB * NHEADS)      // 512
#define NTOK    (NB * S)           // 19200

// 1/sqrt(48) * log2(e): softmax runs in base-2, scale folded into Q at TLE time
#define CSCALE  (0.14433756729740643f * 1.4426950408889634f)

// ---------------------------------------------------------------------------
// Scratch
// ---------------------------------------------------------------------------
__device__ float g_Q[NBH * S * HD];    // [bh][s][48]  (pre-scaled by CSCALE)
__device__ float g_K[NBH * S * HD];    // [bh][s][48]
__device__ float g_V[NBH * S * HD];    // [bh][s][48]
__device__ float g_O[NBH * S * HD];    // [bh][s][48]

#define EX2F(d, s) asm("ex2.approx.ftz.f32 %0, %1;" : "=f"(d) : "f"(s))

// m16n8k8 tf32 mma (sm_80+; works at plain sm_100 target)
__device__ __forceinline__ void mma_tf32(float c[4], const uint32_t a[4],
                                         uint32_t b0, uint32_t b1) {
    asm volatile("mma.sync.aligned.m16n8k8.row.col.f32.tf32.tf32.f32 "
                 "{%0,%1,%2,%3}, {%4,%5,%6,%7}, {%8,%9}, {%0,%1,%2,%3};"
                 : "+f"(c[0]), "+f"(c[1]), "+f"(c[2]), "+f"(c[3])
                 : "r"(a[0]), "r"(a[1]), "r"(a[2]), "r"(a[3]),
                   "r"(b0), "r"(b1));
}

// ---------------------------------------------------------------------------
// TLE q/k/v:  96 threads per token, 2 tokens per block. Register-blocked:
//   step1 thread=jk (8 outs), step2 thread=(a,k) (8 outs), step3 thread=(a,c) (12 outs)
// ---------------------------------------------------------------------------
#define T1S 100   // padded strides (kill bank conflicts)

__global__ void __launch_bounds__(192) tle_qkv_kernel(
    const float* __restrict__ x,
    const float* __restrict__ wq1, const float* __restrict__ wq2,
    const float* __restrict__ wq3, const float* __restrict__ bq,
    const float* __restrict__ wk1, const float* __restrict__ wk2,
    const float* __restrict__ wk3, const float* __restrict__ bk,
    const float* __restrict__ wv1, const float* __restrict__ wv2,
    const float* __restrict__ wv3, const float* __restrict__ bv)
{
    __shared__ float xs[2][C];
    __shared__ float t1[2][8 * T1S];
    __shared__ float t2[2][8 * T1S];
    __shared__ float w1s[64], w2s[64], w3s[144];

    const int tid = threadIdx.x;
    const int tt  = tid / 96;
    const int q   = tid % 96;
    const int tok = blockIdx.x * 2 + tt;
    const int b   = tok / S;
    const int s   = tok % S;
    const int bh0 = b * NHEADS;

    {   // stage x
        const float4* xp = (const float4*)(x + (size_t)tok * C);
        float4* xd = (float4*)xs[tt];
        xd[q] = xp[q];
        xd[q + 96] = xp[q + 96];
    }

    const int a2 = q / 12, k2 = q % 12;   // step-2 role
    const int a3 = q >> 3, c3 = q & 7;    // step-3 role (q < 64)

    const float* W1[3] = {wq1, wk1, wv1};
    const float* W2[3] = {wq2, wk2, wv2};
    const float* W3[3] = {wq3, wk3, wv3};
    const float* BB[3] = {bq,  bk,  bv };

    #pragma unroll 1
    for (int p = 0; p < 3; ++p) {
        __syncthreads();
        for (int i = tid; i < 64; i += 192)  { w1s[i] = W1[p][i]; w2s[i] = W2[p][i]; }
        for (int i = tid; i < 144; i += 192) w3s[i] = W3[p][i];
        __syncthreads();

        // step 1: t1[a][jk] = sum_i w1[a,i] x[i][jk]
        float xv[8];
        #pragma unroll
        for (int i = 0; i < 8; ++i) xv[i] = xs[tt][i * 96 + q];
        #pragma unroll
        for (int a = 0; a < 8; ++a) {
            float acc = 0.f;
            #pragma unroll
            for (int i = 0; i < 8; ++i) acc += w1s[a * 8 + i] * xv[i];
            t1[tt][a * T1S + q] = acc;
        }
        __syncthreads();

        // step 2: t2[a][c][k] = sum_j w2[c,j] t1[a][j*12+k]
        float tv[8];
        #pragma unroll
        for (int j = 0; j < 8; ++j) tv[j] = t1[tt][a2 * T1S + j * 12 + k2];
        #pragma unroll
        for (int cc = 0; cc < 8; ++cc) {
            float acc = 0.f;
            #pragma unroll
            for (int j = 0; j < 8; ++j) acc += w2s[cc * 8 + j] * tv[j];
            t2[tt][a2 * T1S + cc * 12 + k2] = acc;
        }
        __syncthreads();

        // step 3: out[a][c][d] = sum_k w3[d,k] t2 + bias ; scatter to head layout
        if (q < 64) {
            float uv[12];
            #pragma unroll
            for (int k = 0; k < 12; ++k) uv[k] = t2[tt][a3 * T1S + c3 * 12 + k];
            const float* bp = BB[p] + a3 * 96 + c3 * 12;
            #pragma unroll
            for (int d = 0; d < 12; ++d) {
                float acc = bp[d];
                #pragma unroll
                for (int k = 0; k < 12; ++k) acc += w3s[d * 12 + k] * uv[k];
                const int h    = (a3 & 1) * 8 + (c3 & 1) * 4 + (d & 3);
                const int dpos = (a3 >> 1) * 12 + (c3 >> 1) * 3 + (d >> 2);
                const size_t bh = (size_t)(bh0 + h);
                if (p == 0)      g_Q[(bh * S + s) * HD + dpos] = acc * CSCALE;
                else if (p == 1) g_K[(bh * S + s) * HD + dpos] = acc;
                else             g_V[(bh * S + s) * HD + dpos] = acc;
            }
        }
    }
}

// ---------------------------------------------------------------------------
// tf32 mma.sync flash attention.
//   grid (5 q-tiles, 512 bh), 256 threads = 8 warps; warp owns 16 query rows.
//   Per 64-key tile: S = Q K^T (MMA), exp2 in regs (fixed max = 0, scale
//   pre-folded into Q), P via per-warp padded smem, O += P V (MMA).
// ---------------------------------------------------------------------------
#define SQ 52                 // padded row stride for Q/K/V tiles (floats)
#define SP 72                 // padded row stride for P buffers (floats)
#define OFF_K 6656            // 128*SQ
#define OFF_V 9984            // OFF_K + 64*SQ
#define OFF_P 13312           // OFF_V + 64*SQ
#define ATTN_SMEM ((OFF_P + 8 * 16 * SP) * 4)   // 90112 bytes

__global__ void __launch_bounds__(256, 2) attn_kernel()
{
    extern __shared__ float smf[];
    float* const Qs = smf;
    float* const Ks = smf + OFF_K;
    float* const Vs = smf + OFF_V;

    const int tid  = threadIdx.x;
    const int wid  = tid >> 5;
    const int lane = tid & 31;
    const int gid  = lane >> 2;      // row group within mma
    const int tig  = lane & 3;       // thread in group
    float* const Ps = smf + OFF_P + wid * 16 * SP;

    const int hid = blockIdx.y;
    const int q0  = blockIdx.x * 128;
    const float4 z4 = make_float4(0.f, 0.f, 0.f, 0.f);

    // ---- stage Q tile (zero-pad rows >= S) ----
    const float4* __restrict__ Qg = (const float4*)(g_Q + (size_t)hid * S * HD);
    for (int i = tid; i < 128 * 12; i += 256) {
        const int row = i / 12, c4 = i % 12, gr = q0 + row;
        float4 v = (gr < S) ? Qg[gr * 12 + c4] : z4;
        *(float4*)(Qs + row * SQ + c4 * 4) = v;
    }
    __syncthreads();

    // ---- Q fragments in registers (held across all key tiles) ----
    uint32_t qa[6][4];
    {
        const int r0 = wid * 16 + gid;
        #pragma unroll
        for (int ks = 0; ks < 6; ++ks) {
            qa[ks][0] = __float_as_uint(Qs[r0 * SQ + ks * 8 + tig]);
            qa[ks][1] = __float_as_uint(Qs[(r0 + 8) * SQ + ks * 8 + tig]);
            qa[ks][2] = __float_as_uint(Qs[r0 * SQ + ks * 8 + tig + 4]);
            qa[ks][3] = __float_as_uint(Qs[(r0 + 8) * SQ + ks * 8 + tig + 4]);
        }
    }

    float o[6][4];
    #pragma unroll
    for (int n = 0; n < 6; ++n) { o[n][0] = o[n][1] = o[n][2] = o[n][3] = 0.f; }
    float l0 = 0.f, l1 = 0.f;

    const float4* __restrict__ Kg = (const float4*)(g_K + (size_t)hid * S * HD);
    const float4* __restrict__ Vg = (const float4*)(g_V + (size_t)hid * S * HD);

    #pragma unroll 1
    for (int t = 0; t < 10; ++t) {
        const int j0 = t * 64;
        __syncthreads();   // all warps done reading previous K/V (and Ps writes ordered)
        for (int i = tid; i < 64 * 12; i += 256) {
            const int row = i / 12, c4 = i % 12, gr = j0 + row;
            float4 kv = (gr < S) ? Kg[gr * 12 + c4] : z4;
            *(float4*)(Ks + row * SQ + c4 * 4) = kv;
            float4 vv = (gr < S) ? Vg[gr * 12 + c4] : z4;
            *(float4*)(Vs + row * SQ + c4 * 4) = vv;
        }
        __syncthreads();

        // ---- S = Q K^T, then exp2 + row-sum + store P ----
        #pragma unroll
        for (int nb = 0; nb < 8; ++nb) {
            float c[4] = {0.f, 0.f, 0.f, 0.f};
            #pragma unroll
            for (int ks = 0; ks < 6; ++ks) {
                const uint32_t b0 = __float_as_uint(Ks[(nb * 8 + gid) * SQ + ks * 8 + tig]);
                const uint32_t b1 = __float_as_uint(Ks[(nb * 8 + gid) * SQ + ks * 8 + tig + 4]);
                mma_tf32(c, qa[ks], b0, b1);
            }
            const int key0 = j0 + nb * 8 + 2 * tig;
            float p0, p1, p2, p3;
            EX2F(p0, c[0]); EX2F(p1, c[1]); EX2F(p2, c[2]); EX2F(p3, c[3]);
            if (key0     >= S) { p0 = 0.f; p2 = 0.f; }
            if (key0 + 1 >= S) { p1 = 0.f; p3 = 0.f; }
            l0 += p0 + p1;
            l1 += p2 + p3;
            *(float2*)(Ps + gid * SP + nb * 8 + 2 * tig)       = make_float2(p0, p1);
            *(float2*)(Ps + (gid + 8) * SP + nb * 8 + 2 * tig) = make_float2(p2, p3);
        }
        __syncwarp();

        // ---- O += P V ----
        #pragma unroll
        for (int ks = 0; ks < 8; ++ks) {
            uint32_t pa[4];
            pa[0] = __float_as_uint(Ps[gid * SP + ks * 8 + tig]);
            pa[1] = __float_as_uint(Ps[(gid + 8) * SP + ks * 8 + tig]);
            pa[2] = __float_as_uint(Ps[gid * SP + ks * 8 + tig + 4]);
            pa[3] = __float_as_uint(Ps[(gid + 8) * SP + ks * 8 + tig + 4]);
            #pragma unroll
            for (int nb = 0; nb < 6; ++nb) {
                const uint32_t b0 = __float_as_uint(Vs[(ks * 8 + tig) * SQ + nb * 8 + gid]);
                const uint32_t b1 = __float_as_uint(Vs[(ks * 8 + tig + 4) * SQ + nb * 8 + gid]);
                mma_tf32(o[nb], pa, b0, b1);
            }
        }
    }

    // ---- normalize + store ----
    l0 += __shfl_xor_sync(0xFFFFFFFFu, l0, 1);
    l0 += __shfl_xor_sync(0xFFFFFFFFu, l0, 2);
    l1 += __shfl_xor_sync(0xFFFFFFFFu, l1, 1);
    l1 += __shfl_xor_sync(0xFFFFFFFFu, l1, 2);
    const float i0 = 1.f / l0;
    const float i1 = 1.f / l1;
    const int r0 = q0 + wid * 16 + gid;
    const int r1 = r0 + 8;
    float* const Og = g_O + (size_t)hid * S * HD;
    #pragma unroll
    for (int nb = 0; nb < 6; ++nb) {
        if (r0 < S)
            *(float2*)(Og + r0 * HD + nb * 8 + 2 * tig) = make_float2(o[nb][0] * i0, o[nb][1] * i0);
        if (r1 < S)
            *(float2*)(Og + r1 * HD + nb * 8 + 2 * tig) = make_float2(o[nb][2] * i1, o[nb][3] * i1);
    }
}

// ---------------------------------------------------------------------------
// Output TLE (gather heads + 3-mode contraction)
// ---------------------------------------------------------------------------
__global__ void __launch_bounds__(192) tle_o_kernel(
    const float* __restrict__ wo1, const float* __restrict__ wo2,
    const float* __restrict__ wo3, const float* __restrict__ bo,
    float* __restrict__ out)
{
    __shared__ float xs[2][C];
    __shared__ float t1[2][8 * T1S];
    __shared__ float t2[2][8 * T1S];
    __shared__ float w1s[64], w2s[64], w3s[144];

    const int tid = threadIdx.x;
    const int tt  = tid / 96;
    const int q   = tid % 96;
    const int tok = blockIdx.x * 2 + tt;
    const int b   = tok / S;
    const int s   = tok % S;
    const int bh0 = b * NHEADS;

    // gather merge_heads into channel order (a,c,d)
    for (int i = q; i < C; i += 96) {
        const int a = i / 96, r = i % 96, c2 = r / 12, d = r % 12;
        const int h    = (a & 1) * 8 + (c2 & 1) * 4 + (d & 3);
        const int dpos = (a >> 1) * 12 + (c2 >> 1) * 3 + (d >> 2);
        xs[tt][i] = g_O[(((size_t)(bh0 + h)) * S + s) * HD + dpos];
    }
    for (int i = tid; i < 64; i += 192)  { w1s[i] = wo1[i]; w2s[i] = wo2[i]; }
    for (int i = tid; i < 144; i += 192) w3s[i] = wo3[i];
    __syncthreads();

    const int a2 = q / 12, k2 = q % 12;
    const int a3 = q >> 3, c3 = q & 7;

    float xv[8];
    #pragma unroll
    for (int i = 0; i < 8; ++i) xv[i] = xs[tt][i * 96 + q];
    #pragma unroll
    for (int a = 0; a < 8; ++a) {
        float acc = 0.f;
        #pragma unroll
        for (int i = 0; i < 8; ++i) acc += w1s[a * 8 + i] * xv[i];
        t1[tt][a * T1S + q] = acc;
    }
    __syncthreads();

    float tv[8];
    #pragma unroll
    for (int j = 0; j < 8; ++j) tv[j] = t1[tt][a2 * T1S + j * 12 + k2];
    #pragma unroll
    for (int cc = 0; cc < 8; ++cc) {
        float acc = 0.f;
        #pragma unroll
        for (int j = 0; j < 8; ++j) acc += w2s[cc * 8 + j] * tv[j];
        t2[tt][a2 * T1S + cc * 12 + k2] = acc;
    }
    __syncthreads();

    if (q < 64) {
        float uv[12];
        #pragma unroll
        for (int k = 0; k < 12; ++k) uv[k] = t2[tt][a3 * T1S + c3 * 12 + k];
        const float* bp = bo + a3 * 96 + c3 * 12;
        float* op = out + (size_t)tok * C + a3 * 96 + c3 * 12;
        #pragma unroll
        for (int d = 0; d < 12; ++d) {
            float acc = bp[d];
            #pragma unroll
            for (int k = 0; k < 12; ++k) acc += w3s[d * 12 + k] * uv[k];
            op[d] = acc;
        }
    }
}

// ---------------------------------------------------------------------------
// Launch
// ---------------------------------------------------------------------------
extern "C" void kernel_launch(void* const* d_in, const int* in_sizes, int n_in,
                              void* d_out, int out_size)
{
    const float* x   = (const float*)d_in[0];
    const float* wq1 = (const float*)d_in[1];
    const float* wq2 = (const float*)d_in[2];
    const float* wq3 = (const float*)d_in[3];
    const float* bq  = (const float*)d_in[4];
    const float* wk1 = (const float*)d_in[5];
    const float* wk2 = (const float*)d_in[6];
    const float* wk3 = (const float*)d_in[7];
    const float* bk  = (const float*)d_in[8];
    const float* wv1 = (const float*)d_in[9];
    const float* wv2 = (const float*)d_in[10];
    const float* wv3 = (const float*)d_in[11];
    const float* bv  = (const float*)d_in[12];
    const float* wo1 = (const float*)d_in[13];
    const float* wo2 = (const float*)d_in[14];
    const float* wo3 = (const float*)d_in[15];
    const float* bo  = (const float*)d_in[16];
    float* out = (float*)d_out;

    cudaFuncSetAttribute(attn_kernel,
                         cudaFuncAttributeMaxDynamicSharedMemorySize, ATTN_SMEM);

    tle_qkv_kernel<<<NTOK / 2, 192>>>(x, wq1, wq2, wq3, bq,
                                         wk1, wk2, wk3, bk,
                                         wv1, wv2, wv3, bv);

    attn_kernel<<<dim3(5, NBH), 256, ATTN_SMEM>>>();

    tle_o_kernel<<<NTOK / 2, 192>>>(wo1, wo2, wo3, bo, out);
}

// round 4
// speedup vs baseline: 2.4174x; 1.0001x over previous
#include <cuda_runtime.h>
#include <cstdint>

// ---------------------------------------------------------------------------
// Problem constants
// ---------------------------------------------------------------------------
#define NB      32
#define S       600
#define C       768
#define HD      48
#define NHEADS  16
#define NBH     (NB * NHEADS)      // 512
#define NTOK    (NB * S)           // 19200

// 1/sqrt(48) * log2(e): softmax runs in base-2, scale folded into Q at TLE time
#define CSCALE  (0.14433756729740643f * 1.4426950408889634f)

// ---------------------------------------------------------------------------
// Scratch
// ---------------------------------------------------------------------------
__device__ float g_Q[NBH * S * HD];    // [bh][s][48]  (pre-scaled by CSCALE)
__device__ float g_K[NBH * S * HD];    // [bh][s][48]
__device__ float g_V[NBH * S * HD];    // [bh][s][48]
__device__ float g_O[NBH * S * HD];    // [bh][s][48]

#define EX2F(d, s) asm("ex2.approx.ftz.f32 %0, %1;" : "=f"(d) : "f"(s))

// m16n8k8 tf32 mma (sm_80+; works at plain sm_100 target)
__device__ __forceinline__ void mma_tf32(float c[4], const uint32_t a[4],
                                         uint32_t b0, uint32_t b1) {
    asm volatile("mma.sync.aligned.m16n8k8.row.col.f32.tf32.tf32.f32 "
                 "{%0,%1,%2,%3}, {%4,%5,%6,%7}, {%8,%9}, {%0,%1,%2,%3};"
                 : "+f"(c[0]), "+f"(c[1]), "+f"(c[2]), "+f"(c[3])
                 : "r"(a[0]), "r"(a[1]), "r"(a[2]), "r"(a[3]),
                   "r"(b0), "r"(b1));
}

// ---------------------------------------------------------------------------
// TLE q/k/v:  96 threads per token, 2 tokens per block. Register-blocked:
//   step1 thread=jk (8 outs), step2 thread=(a,k) (8 outs), step3 thread=(a,c) (12 outs)
// ---------------------------------------------------------------------------
#define T1S 100   // padded strides (kill bank conflicts)

__global__ void __launch_bounds__(192) tle_qkv_kernel(
    const float* __restrict__ x,
    const float* __restrict__ wq1, const float* __restrict__ wq2,
    const float* __restrict__ wq3, const float* __restrict__ bq,
    const float* __restrict__ wk1, const float* __restrict__ wk2,
    const float* __restrict__ wk3, const float* __restrict__ bk,
    const float* __restrict__ wv1, const float* __restrict__ wv2,
    const float* __restrict__ wv3, const float* __restrict__ bv)
{
    __shared__ float xs[2][C];
    __shared__ float t1[2][8 * T1S];
    __shared__ float t2[2][8 * T1S];
    __shared__ float w1s[64], w2s[64], w3s[144];

    const int tid = threadIdx.x;
    const int tt  = tid / 96;
    const int q   = tid % 96;
    const int tok = blockIdx.x * 2 + tt;
    const int b   = tok / S;
    const int s   = tok % S;
    const int bh0 = b * NHEADS;

    {   // stage x
        const float4* xp = (const float4*)(x + (size_t)tok * C);
        float4* xd = (float4*)xs[tt];
        xd[q] = xp[q];
        xd[q + 96] = xp[q + 96];
    }

    const int a2 = q / 12, k2 = q % 12;   // step-2 role
    const int a3 = q >> 3, c3 = q & 7;    // step-3 role (q < 64)

    const float* W1[3] = {wq1, wk1, wv1};
    const float* W2[3] = {wq2, wk2, wv2};
    const float* W3[3] = {wq3, wk3, wv3};
    const float* BB[3] = {bq,  bk,  bv };

    #pragma unroll 1
    for (int p = 0; p < 3; ++p) {
        __syncthreads();
        for (int i = tid; i < 64; i += 192)  { w1s[i] = W1[p][i]; w2s[i] = W2[p][i]; }
        for (int i = tid; i < 144; i += 192) w3s[i] = W3[p][i];
        __syncthreads();

        // step 1: t1[a][jk] = sum_i w1[a,i] x[i][jk]
        float xv[8];
        #pragma unroll
        for (int i = 0; i < 8; ++i) xv[i] = xs[tt][i * 96 + q];
        #pragma unroll
        for (int a = 0; a < 8; ++a) {
            float acc = 0.f;
            #pragma unroll
            for (int i = 0; i < 8; ++i) acc += w1s[a * 8 + i] * xv[i];
            t1[tt][a * T1S + q] = acc;
        }
        __syncthreads();

        // step 2: t2[a][c][k] = sum_j w2[c,j] t1[a][j*12+k]
        float tv[8];
        #pragma unroll
        for (int j = 0; j < 8; ++j) tv[j] = t1[tt][a2 * T1S + j * 12 + k2];
        #pragma unroll
        for (int cc = 0; cc < 8; ++cc) {
            float acc = 0.f;
            #pragma unroll
            for (int j = 0; j < 8; ++j) acc += w2s[cc * 8 + j] * tv[j];
            t2[tt][a2 * T1S + cc * 12 + k2] = acc;
        }
        __syncthreads();

        // step 3: out[a][c][d] = sum_k w3[d,k] t2 + bias ; scatter to head layout
        if (q < 64) {
            float uv[12];
            #pragma unroll
            for (int k = 0; k < 12; ++k) uv[k] = t2[tt][a3 * T1S + c3 * 12 + k];
            const float* bp = BB[p] + a3 * 96 + c3 * 12;
            #pragma unroll
            for (int d = 0; d < 12; ++d) {
                float acc = bp[d];
                #pragma unroll
                for (int k = 0; k < 12; ++k) acc += w3s[d * 12 + k] * uv[k];
                const int h    = (a3 & 1) * 8 + (c3 & 1) * 4 + (d & 3);
                const int dpos = (a3 >> 1) * 12 + (c3 >> 1) * 3 + (d >> 2);
                const size_t bh = (size_t)(bh0 + h);
                if (p == 0)      g_Q[(bh * S + s) * HD + dpos] = acc * CSCALE;
                else if (p == 1) g_K[(bh * S + s) * HD + dpos] = acc;
                else             g_V[(bh * S + s) * HD + dpos] = acc;
            }
        }
    }
}

// ---------------------------------------------------------------------------
// tf32 mma.sync flash attention.
//   grid (5 q-tiles, 512 bh), 256 threads = 8 warps; warp owns 16 query rows.
//   Per 64-key tile: S = Q K^T (MMA), exp2 in regs (fixed max = 0, scale
//   pre-folded into Q), P via per-warp padded smem, O += P V (MMA).
// ---------------------------------------------------------------------------
#define SQ 52                 // padded row stride for Q/K/V tiles (floats)
#define SP 72                 // padded row stride for P buffers (floats)
#define OFF_K 6656            // 128*SQ
#define OFF_V 9984            // OFF_K + 64*SQ
#define OFF_P 13312           // OFF_V + 64*SQ
#define ATTN_SMEM ((OFF_P + 8 * 16 * SP) * 4)   // 90112 bytes

__global__ void __launch_bounds__(256, 2) attn_kernel()
{
    extern __shared__ float smf[];
    float* const Qs = smf;
    float* const Ks = smf + OFF_K;
    float* const Vs = smf + OFF_V;

    const int tid  = threadIdx.x;
    const int wid  = tid >> 5;
    const int lane = tid & 31;
    const int gid  = lane >> 2;      // row group within mma
    const int tig  = lane & 3;       // thread in group
    float* const Ps = smf + OFF_P + wid * 16 * SP;

    const int hid = blockIdx.y;
    const int q0  = blockIdx.x * 128;
    const float4 z4 = make_float4(0.f, 0.f, 0.f, 0.f);

    // ---- stage Q tile (zero-pad rows >= S) ----
    const float4* __restrict__ Qg = (const float4*)(g_Q + (size_t)hid * S * HD);
    for (int i = tid; i < 128 * 12; i += 256) {
        const int row = i / 12, c4 = i % 12, gr = q0 + row;
        float4 v = (gr < S) ? Qg[gr * 12 + c4] : z4;
        *(float4*)(Qs + row * SQ + c4 * 4) = v;
    }
    __syncthreads();

    // ---- Q fragments in registers (held across all key tiles) ----
    uint32_t qa[6][4];
    {
        const int r0 = wid * 16 + gid;
        #pragma unroll
        for (int ks = 0; ks < 6; ++ks) {
            qa[ks][0] = __float_as_uint(Qs[r0 * SQ + ks * 8 + tig]);
            qa[ks][1] = __float_as_uint(Qs[(r0 + 8) * SQ + ks * 8 + tig]);
            qa[ks][2] = __float_as_uint(Qs[r0 * SQ + ks * 8 + tig + 4]);
            qa[ks][3] = __float_as_uint(Qs[(r0 + 8) * SQ + ks * 8 + tig + 4]);
        }
    }

    float o[6][4];
    #pragma unroll
    for (int n = 0; n < 6; ++n) { o[n][0] = o[n][1] = o[n][2] = o[n][3] = 0.f; }
    float l0 = 0.f, l1 = 0.f;

    const float4* __restrict__ Kg = (const float4*)(g_K + (size_t)hid * S * HD);
    const float4* __restrict__ Vg = (const float4*)(g_V + (size_t)hid * S * HD);

    #pragma unroll 1
    for (int t = 0; t < 10; ++t) {
        const int j0 = t * 64;
        __syncthreads();   // all warps done reading previous K/V (and Ps writes ordered)
        for (int i = tid; i < 64 * 12; i += 256) {
            const int row = i / 12, c4 = i % 12, gr = j0 + row;
            float4 kv = (gr < S) ? Kg[gr * 12 + c4] : z4;
            *(float4*)(Ks + row * SQ + c4 * 4) = kv;
            float4 vv = (gr < S) ? Vg[gr * 12 + c4] : z4;
            *(float4*)(Vs + row * SQ + c4 * 4) = vv;
        }
        __syncthreads();

        // ---- S = Q K^T, then exp2 + row-sum + store P ----
        #pragma unroll
        for (int nb = 0; nb < 8; ++nb) {
            float c[4] = {0.f, 0.f, 0.f, 0.f};
            #pragma unroll
            for (int ks = 0; ks < 6; ++ks) {
                const uint32_t b0 = __float_as_uint(Ks[(nb * 8 + gid) * SQ + ks * 8 + tig]);
                const uint32_t b1 = __float_as_uint(Ks[(nb * 8 + gid) * SQ + ks * 8 + tig + 4]);
                mma_tf32(c, qa[ks], b0, b1);
            }
            const int key0 = j0 + nb * 8 + 2 * tig;
            float p0, p1, p2, p3;
            EX2F(p0, c[0]); EX2F(p1, c[1]); EX2F(p2, c[2]); EX2F(p3, c[3]);
            if (key0     >= S) { p0 = 0.f; p2 = 0.f; }
            if (key0 + 1 >= S) { p1 = 0.f; p3 = 0.f; }
            l0 += p0 + p1;
            l1 += p2 + p3;
            *(float2*)(Ps + gid * SP + nb * 8 + 2 * tig)       = make_float2(p0, p1);
            *(float2*)(Ps + (gid + 8) * SP + nb * 8 + 2 * tig) = make_float2(p2, p3);
        }
        __syncwarp();

        // ---- O += P V ----
        #pragma unroll
        for (int ks = 0; ks < 8; ++ks) {
            uint32_t pa[4];
            pa[0] = __float_as_uint(Ps[gid * SP + ks * 8 + tig]);
            pa[1] = __float_as_uint(Ps[(gid + 8) * SP + ks * 8 + tig]);
            pa[2] = __float_as_uint(Ps[gid * SP + ks * 8 + tig + 4]);
            pa[3] = __float_as_uint(Ps[(gid + 8) * SP + ks * 8 + tig + 4]);
            #pragma unroll
            for (int nb = 0; nb < 6; ++nb) {
                const uint32_t b0 = __float_as_uint(Vs[(ks * 8 + tig) * SQ + nb * 8 + gid]);
                const uint32_t b1 = __float_as_uint(Vs[(ks * 8 + tig + 4) * SQ + nb * 8 + gid]);
                mma_tf32(o[nb], pa, b0, b1);
            }
        }
    }

    // ---- normalize + store ----
    l0 += __shfl_xor_sync(0xFFFFFFFFu, l0, 1);
    l0 += __shfl_xor_sync(0xFFFFFFFFu, l0, 2);
    l1 += __shfl_xor_sync(0xFFFFFFFFu, l1, 1);
    l1 += __shfl_xor_sync(0xFFFFFFFFu, l1, 2);
    const float i0 = 1.f / l0;
    const float i1 = 1.f / l1;
    const int r0 = q0 + wid * 16 + gid;
    const int r1 = r0 + 8;
    float* const Og = g_O + (size_t)hid * S * HD;
    #pragma unroll
    for (int nb = 0; nb < 6; ++nb) {
        if (r0 < S)
            *(float2*)(Og + r0 * HD + nb * 8 + 2 * tig) = make_float2(o[nb][0] * i0, o[nb][1] * i0);
        if (r1 < S)
            *(float2*)(Og + r1 * HD + nb * 8 + 2 * tig) = make_float2(o[nb][2] * i1, o[nb][3] * i1);
    }
}

// ---------------------------------------------------------------------------
// Output TLE (gather heads + 3-mode contraction)
// ---------------------------------------------------------------------------
__global__ void __launch_bounds__(192) tle_o_kernel(
    const float* __restrict__ wo1, const float* __restrict__ wo2,
    const float* __restrict__ wo3, const float* __restrict__ bo,
    float* __restrict__ out)
{
    __shared__ float xs[2][C];
    __shared__ float t1[2][8 * T1S];
    __shared__ float t2[2][8 * T1S];
    __shared__ float w1s[64], w2s[64], w3s[144];

    const int tid = threadIdx.x;
    const int tt  = tid / 96;
    const int q   = tid % 96;
    const int tok = blockIdx.x * 2 + tt;
    const int b   = tok / S;
    const int s   = tok % S;
    const int bh0 = b * NHEADS;

    // gather merge_heads into channel order (a,c,d)
    for (int i = q; i < C; i += 96) {
        const int a = i / 96, r = i % 96, c2 = r / 12, d = r % 12;
        const int h    = (a & 1) * 8 + (c2 & 1) * 4 + (d & 3);
        const int dpos = (a >> 1) * 12 + (c2 >> 1) * 3 + (d >> 2);
        xs[tt][i] = g_O[(((size_t)(bh0 + h)) * S + s) * HD + dpos];
    }
    for (int i = tid; i < 64; i += 192)  { w1s[i] = wo1[i]; w2s[i] = wo2[i]; }
    for (int i = tid; i < 144; i += 192) w3s[i] = wo3[i];
    __syncthreads();

    const int a2 = q / 12, k2 = q % 12;
    const int a3 = q >> 3, c3 = q & 7;

    float xv[8];
    #pragma unroll
    for (int i = 0; i < 8; ++i) xv[i] = xs[tt][i * 96 + q];
    #pragma unroll
    for (int a = 0; a < 8; ++a) {
        float acc = 0.f;
        #pragma unroll
        for (int i = 0; i < 8; ++i) acc += w1s[a * 8 + i] * xv[i];
        t1[tt][a * T1S + q] = acc;
    }
    __syncthreads();

    float tv[8];
    #pragma unroll
    for (int j = 0; j < 8; ++j) tv[j] = t1[tt][a2 * T1S + j * 12 + k2];
    #pragma unroll
    for (int cc = 0; cc < 8; ++cc) {
        float acc = 0.f;
        #pragma unroll
        for (int j = 0; j < 8; ++j) acc += w2s[cc * 8 + j] * tv[j];
        t2[tt][a2 * T1S + cc * 12 + k2] = acc;
    }
    __syncthreads();

    if (q < 64) {
        float uv[12];
        #pragma unroll
        for (int k = 0; k < 12; ++k) uv[k] = t2[tt][a3 * T1S + c3 * 12 + k];
        const float* bp = bo + a3 * 96 + c3 * 12;
        float* op = out + (size_t)tok * C + a3 * 96 + c3 * 12;
        #pragma unroll
        for (int d = 0; d < 12; ++d) {
            float acc = bp[d];
            #pragma unroll
            for (int k = 0; k < 12; ++k) acc += w3s[d * 12 + k] * uv[k];
            op[d] = acc;
        }
    }
}

// ---------------------------------------------------------------------------
// Launch
// ---------------------------------------------------------------------------
extern "C" void kernel_launch(void* const* d_in, const int* in_sizes, int n_in,
                              void* d_out, int out_size)
{
    const float* x   = (const float*)d_in[0];
    const float* wq1 = (const float*)d_in[1];
    const float* wq2 = (const float*)d_in[2];
    const float* wq3 = (const float*)d_in[3];
    const float* bq  = (const float*)d_in[4];
    const float* wk1 = (const float*)d_in[5];
    const float* wk2 = (const float*)d_in[6];
    const float* wk3 = (const float*)d_in[7];
    const float* bk  = (const float*)d_in[8];
    const float* wv1 = (const float*)d_in[9];
    const float* wv2 = (const float*)d_in[10];
    const float* wv3 = (const float*)d_in[11];
    const float* bv  = (const float*)d_in[12];
    const float* wo1 = (const float*)d_in[13];
    const float* wo2 = (const float*)d_in[14];
    const float* wo3 = (const float*)d_in[15];
    const float* bo  = (const float*)d_in[16];
    float* out = (float*)d_out;

    cudaFuncSetAttribute(attn_kernel,
                         cudaFuncAttributeMaxDynamicSharedMemorySize, ATTN_SMEM);

    tle_qkv_kernel<<<NTOK / 2, 192>>>(x, wq1, wq2, wq3, bq,
                                         wk1, wk2, wk3, bk,
                                         wv1, wv2, wv3, bv);

    attn_kernel<<<dim3(5, NBH), 256, ATTN_SMEM>>>();

    tle_o_kernel<<<NTOK / 2, 192>>>(wo1, wo2, wo3, bo, out);
}

// round 5
// speedup vs baseline: 3.7283x; 1.5423x over previous
#include <cuda_runtime.h>
#include <cuda_fp16.h>
#include <cstdint>

// ---------------------------------------------------------------------------
// Problem constants
// ---------------------------------------------------------------------------
#define NB      32
#define S       600
#define C       768
#define HD      48
#define NHEADS  16
#define NBH     (NB * NHEADS)      // 512
#define NTOK    (NB * S)           // 19200

// 1/sqrt(48) * log2(e): softmax runs in base-2, scale folded into Q at TLE time
#define CSCALE  (0.14433756729740643f * 1.4426950408889634f)

// ---------------------------------------------------------------------------
// Scratch (fp16 Q/K/V; fp32 O). g_Qh padded: attn loads Q rows 600..639 blindly.
// ---------------------------------------------------------------------------
__device__ __half g_Qh[NBH * S * HD + 2048];
__device__ __half g_Kh[NBH * S * HD];
__device__ __half g_Vh[NBH * S * HD];
__device__ float  g_O [NBH * S * HD];

#define EX2F(d, s) asm("ex2.approx.ftz.f32 %0, %1;" : "=f"(d) : "f"(s))

// m16n8k16 f16 mma with f32 accumulate (sm_80+; valid at plain sm_100 target)
__device__ __forceinline__ void mma_f16(float c[4], const uint32_t a[4],
                                        uint32_t b0, uint32_t b1) {
    asm volatile("mma.sync.aligned.m16n8k16.row.col.f32.f16.f16.f32 "
                 "{%0,%1,%2,%3}, {%4,%5,%6,%7}, {%8,%9}, {%0,%1,%2,%3};"
                 : "+f"(c[0]), "+f"(c[1]), "+f"(c[2]), "+f"(c[3])
                 : "r"(a[0]), "r"(a[1]), "r"(a[2]), "r"(a[3]),
                   "r"(b0), "r"(b1));
}

// ---------------------------------------------------------------------------
// TLE q/k/v: one warp per token, 4 tokens per 128-thread block.
//   x (768 f32) held in registers across all three projections.
//   Steps communicate via warp-private smem with stride 108 (== 12 mod 32:
//   step-1/step-2 access patterns provably bank-conflict-free).
//   Outputs staged per-warp in head layout, then written as uint4 (8 halves).
// ---------------------------------------------------------------------------
#define TST 108

__global__ void __launch_bounds__(128) tle_qkv_kernel(
    const float* __restrict__ x,
    const float* __restrict__ wq1, const float* __restrict__ wq2,
    const float* __restrict__ wq3, const float* __restrict__ bq,
    const float* __restrict__ wk1, const float* __restrict__ wk2,
    const float* __restrict__ wk3, const float* __restrict__ bk,
    const float* __restrict__ wv1, const float* __restrict__ wv2,
    const float* __restrict__ wv3, const float* __restrict__ bv)
{
    __shared__ float wS[816];          // 3 x (w1 64 | w2 64 | w3 144)
    __shared__ float T1[4][864];
    __shared__ float T2[4][864];

    const int tid  = threadIdx.x;
    const int w    = tid >> 5;
    const int lane = tid & 31;
    const int tok  = blockIdx.x * 4 + w;
    const int b    = tok / S;
    const int s    = tok - b * S;
    const int bh0  = b * NHEADS;

    {
        const float* Wsrc[9] = {wq1, wq2, wq3, wk1, wk2, wk3, wv1, wv2, wv3};
        for (int idx = tid; idx < 816; idx += 128) {
            const int p = idx / 272, r = idx - p * 272;
            float v;
            if (r < 64)       v = Wsrc[3 * p][r];
            else if (r < 128) v = Wsrc[3 * p + 1][r - 64];
            else              v = Wsrc[3 * p + 2][r - 128];
            wS[idx] = v;
        }
    }

    // x into registers: xv[i][m] = x[i*96 + lane + 32m]  (coalesced)
    float xv[24];
    {
        const float* xp = x + (size_t)tok * C;
        #pragma unroll
        for (int m = 0; m < 3; ++m)
            #pragma unroll
            for (int i = 0; i < 8; ++i)
                xv[i * 3 + m] = xp[i * 96 + lane + 32 * m];
    }
    __syncthreads();

    float* const T1w = T1[w];
    float* const T2w = T2[w];

    #pragma unroll
    for (int p = 0; p < 3; ++p) {
        const float* w1 = wS + p * 272;
        const float* w2 = w1 + 64;
        const float* w3 = w1 + 128;
        const float* bp = (p == 0) ? bq : (p == 1) ? bk : bv;
        __half* gdst    = (p == 0) ? g_Qh : (p == 1) ? g_Kh : g_Vh;

        // step 1: t1[a][jk] = sum_i w1[a,i] x[i][jk]
        #pragma unroll
        for (int a = 0; a < 8; ++a) {
            float wr[8];
            #pragma unroll
            for (int i = 0; i < 8; ++i) wr[i] = w1[a * 8 + i];
            #pragma unroll
            for (int m = 0; m < 3; ++m) {
                float acc = 0.f;
                #pragma unroll
                for (int i = 0; i < 8; ++i) acc += wr[i] * xv[i * 3 + m];
                T1w[a * TST + lane + 32 * m] = acc;
            }
        }
        __syncwarp();

        // step 2: t2[a][c*12+k] = sum_j w2[c,j] t1[a][j*12+k]
        #pragma unroll
        for (int m = 0; m < 3; ++m) {
            const int r2 = lane + 32 * m;
            const int a2 = r2 / 12, k2 = r2 - a2 * 12;
            float tv[8];
            #pragma unroll
            for (int j = 0; j < 8; ++j) tv[j] = T1w[a2 * TST + j * 12 + k2];
            #pragma unroll
            for (int cc = 0; cc < 8; ++cc) {
                float acc = 0.f;
                #pragma unroll
                for (int j = 0; j < 8; ++j) acc += w2[cc * 8 + j] * tv[j];
                T2w[a2 * TST + cc * 12 + k2] = acc;
            }
        }
        __syncwarp();

        // step 3: + bias, convert to half, stage in (h, dpos) head layout
        __half* const stg = (__half*)T1w;
        #pragma unroll
        for (int m = 0; m < 2; ++m) {
            const int r3 = lane + 32 * m;
            const int a3 = r3 >> 3, c3 = r3 & 7;
            float uv[12];
            #pragma unroll
            for (int k = 0; k < 12; ++k) uv[k] = T2w[a3 * TST + c3 * 12 + k];
            const float* bb = bp + a3 * 96 + c3 * 12;
            #pragma unroll
            for (int d = 0; d < 12; ++d) {
                float acc = bb[d];
                #pragma unroll
                for (int k = 0; k < 12; ++k) acc += w3[d * 12 + k] * uv[k];
                if (p == 0) acc *= CSCALE;
                const int h    = (a3 & 1) * 8 + (c3 & 1) * 4 + (d & 3);
                const int dpos = (a3 >> 1) * 12 + (c3 >> 1) * 3 + (d >> 2);
                stg[h * 48 + dpos] = __float2half_rn(acc);
            }
        }
        __syncwarp();

        // coalesced write: 96 uint4 (= 768 halves), 3 per lane
        const uint4* srcv = (const uint4*)stg;
        #pragma unroll
        for (int m = 0; m < 3; ++m) {
            const int v = lane + 32 * m;
            const int head = v / 6, off = v - head * 6;
            uint4* dv = (uint4*)(gdst + ((size_t)(bh0 + head) * S + s) * HD);
            dv[off] = srcv[v];
        }
        __syncwarp();
    }
}

// ---------------------------------------------------------------------------
// fp16 mma.sync flash attention.
//   grid (5 q-tiles, 512 bh), 256 thr = 8 warps; warp owns 16 query rows.
//   Q fragments loaded straight from gmem (held across all 10 key tiles).
//   Per 64-key tile: QK^T (3 k16 mmas x 8 nb), exp2 (fixed max=0, scale
//   pre-folded), P -> per-warp smem half2, PV (4 ks x 6 nb) with V staged
//   transposed so B fragments are contiguous half2. All strides conflict-free.
// ---------------------------------------------------------------------------
#define SKH 56     // K tile row stride (halves)
#define SVT 72     // Vt row stride (halves)
#define SPH 72     // P row stride (halves)

__global__ void __launch_bounds__(256) attn_kernel()
{
    __shared__ __half Ks[64 * SKH];        // 7168 B
    __shared__ __half Vt[48 * SVT];        // 6912 B  (dim-major)
    __shared__ __half Ps[8][16 * SPH];     // 18432 B (per warp)

    const int tid  = threadIdx.x;
    const int wid  = tid >> 5;
    const int lane = tid & 31;
    const int gid  = lane >> 2;
    const int tig  = lane & 3;
    const int hid  = blockIdx.y;
    const int q0   = blockIdx.x * 128;

    // ---- Q fragments straight from gmem (rows >= S read pad: harmless) ----
    uint32_t qa[3][4];
    {
        const __half* Q0 = g_Qh + ((size_t)hid * S + (q0 + wid * 16 + gid)) * HD;
        const __half* Q8 = Q0 + 8 * HD;
        #pragma unroll
        for (int ks = 0; ks < 3; ++ks) {
            qa[ks][0] = *(const uint32_t*)(Q0 + ks * 16 + 2 * tig);
            qa[ks][1] = *(const uint32_t*)(Q8 + ks * 16 + 2 * tig);
            qa[ks][2] = *(const uint32_t*)(Q0 + ks * 16 + 8 + 2 * tig);
            qa[ks][3] = *(const uint32_t*)(Q8 + ks * 16 + 8 + 2 * tig);
        }
    }

    float o[6][4];
    #pragma unroll
    for (int n = 0; n < 6; ++n) { o[n][0] = o[n][1] = o[n][2] = o[n][3] = 0.f; }
    float l0 = 0.f, l1 = 0.f;

    const __half* const Kg = g_Kh + (size_t)hid * S * HD;
    const __half* const Vg = g_Vh + (size_t)hid * S * HD;
    __half* const Pw = Ps[wid];

    #pragma unroll 1
    for (int t = 0; t < 10; ++t) {
        const int j0 = t * 64;
        __syncthreads();
        // stage K rows + V transposed (V zero-padded: avoids 0*NaN in PV)
        for (int u = tid; u < 1536; u += 256) {
            const int row = u / 24, cu = u - row * 24, gr = j0 + row;
            const uint32_t kv = (gr < S) ? *(const uint32_t*)(Kg + gr * HD + 2 * cu) : 0u;
            *(uint32_t*)&Ks[row * SKH + 2 * cu] = kv;
            const uint32_t vv = (gr < S) ? *(const uint32_t*)(Vg + gr * HD + 2 * cu) : 0u;
            const __half2 h2 = *(const __half2*)&vv;
            Vt[(2 * cu) * SVT + row]     = __low2half(h2);
            Vt[(2 * cu + 1) * SVT + row] = __high2half(h2);
        }
        __syncthreads();

        // ---- S = Q K^T, exp2, row-sum, store P ----
        #pragma unroll
        for (int nb = 0; nb < 8; ++nb) {
            float c[4] = {0.f, 0.f, 0.f, 0.f};
            const __half* krow = Ks + (nb * 8 + gid) * SKH;
            #pragma unroll
            for (int ks = 0; ks < 3; ++ks) {
                const uint32_t b0 = *(const uint32_t*)(krow + ks * 16 + 2 * tig);
                const uint32_t b1 = *(const uint32_t*)(krow + ks * 16 + 8 + 2 * tig);
                mma_f16(c, qa[ks], b0, b1);
            }
            const int key0 = j0 + nb * 8 + 2 * tig;
            float p0, p1, p2, p3;
            EX2F(p0, c[0]); EX2F(p1, c[1]); EX2F(p2, c[2]); EX2F(p3, c[3]);
            if (key0     >= S) { p0 = 0.f; p2 = 0.f; }
            if (key0 + 1 >= S) { p1 = 0.f; p3 = 0.f; }
            l0 += p0 + p1;
            l1 += p2 + p3;
            *(__half2*)&Pw[gid * SPH + nb * 8 + 2 * tig]       = __floats2half2_rn(p0, p1);
            *(__half2*)&Pw[(gid + 8) * SPH + nb * 8 + 2 * tig] = __floats2half2_rn(p2, p3);
        }
        __syncwarp();

        // ---- O += P V ----
        #pragma unroll
        for (int ks = 0; ks < 4; ++ks) {
            uint32_t pa[4];
            pa[0] = *(const uint32_t*)&Pw[gid * SPH + ks * 16 + 2 * tig];
            pa[1] = *(const uint32_t*)&Pw[(gid + 8) * SPH + ks * 16 + 2 * tig];
            pa[2] = *(const uint32_t*)&Pw[gid * SPH + ks * 16 + 8 + 2 * tig];
            pa[3] = *(const uint32_t*)&Pw[(gid + 8) * SPH + ks * 16 + 8 + 2 * tig];
            #pragma unroll
            for (int nb = 0; nb < 6; ++nb) {
                const __half* vrow = Vt + (nb * 8 + gid) * SVT;
                const uint32_t b0 = *(const uint32_t*)(vrow + ks * 16 + 2 * tig);
                const uint32_t b1 = *(const uint32_t*)(vrow + ks * 16 + 8 + 2 * tig);
                mma_f16(o[nb], pa, b0, b1);
            }
        }
    }

    // ---- normalize + store (f32 O) ----
    l0 += __shfl_xor_sync(0xFFFFFFFFu, l0, 1);
    l0 += __shfl_xor_sync(0xFFFFFFFFu, l0, 2);
    l1 += __shfl_xor_sync(0xFFFFFFFFu, l1, 1);
    l1 += __shfl_xor_sync(0xFFFFFFFFu, l1, 2);
    const float i0 = 1.f / l0;
    const float i1 = 1.f / l1;
    const int r0 = q0 + wid * 16 + gid;
    const int r1 = r0 + 8;
    float* const Og = g_O + (size_t)hid * S * HD;
    #pragma unroll
    for (int nb = 0; nb < 6; ++nb) {
        if (r0 < S)
            *(float2*)(Og + r0 * HD + nb * 8 + 2 * tig) = make_float2(o[nb][0] * i0, o[nb][1] * i0);
        if (r1 < S)
            *(float2*)(Og + r1 * HD + nb * 8 + 2 * tig) = make_float2(o[nb][2] * i1, o[nb][3] * i1);
    }
}

// ---------------------------------------------------------------------------
// Output TLE: warp per token. Gather = dense float4 runs within head segments
// (no read amplification) scattered into smem; contraction as in tle_qkv;
// output written as dense float4 runs (channel-major).
// ---------------------------------------------------------------------------
__global__ void __launch_bounds__(128) tle_o_kernel(
    const float* __restrict__ wo1, const float* __restrict__ wo2,
    const float* __restrict__ wo3, const float* __restrict__ bo,
    float* __restrict__ out)
{
    __shared__ float wS[272];
    __shared__ float T1[4][864];
    __shared__ float T2[4][864];

    const int tid  = threadIdx.x;
    const int w    = tid >> 5;
    const int lane = tid & 31;
    const int tok  = blockIdx.x * 4 + w;
    const int b    = tok / S;
    const int s    = tok - b * S;
    const int bh0  = b * NHEADS;

    for (int idx = tid; idx < 272; idx += 128) {
        wS[idx] = (idx < 64) ? wo1[idx] : (idx < 128) ? wo2[idx - 64] : wo3[idx - 128];
    }

    // gather merge_heads: 192 float4 segment reads -> channel-order smem
    float* const xsw = T2[w];
    #pragma unroll
    for (int m = 0; m < 6; ++m) {
        const int v = lane + 32 * m;            // 0..191
        const int head = v / 12, off = v - head * 12;
        const float4 f = ((const float4*)(g_O + ((size_t)(bh0 + head) * S + s) * HD))[off];
        const int h1 = head >> 3, h2 = (head >> 2) & 1, h3 = head & 3;
        const int dp0 = off * 4;
        #pragma unroll
        for (int jj = 0; jj < 4; ++jj) {
            const int dpos = dp0 + jj;
            const int x1 = dpos / 12, rr = dpos - x1 * 12;
            const int y1 = rr / 3,   z1 = rr - y1 * 3;
            const int chan = (2 * x1 + h1) * 96 + (2 * y1 + h2) * 12 + (4 * z1 + h3);
            xsw[chan] = (jj == 0) ? f.x : (jj == 1) ? f.y : (jj == 2) ? f.z : f.w;
        }
    }
    __syncthreads();   // weights ready (block) + xs ready (warp)

    const float* w1 = wS;
    const float* w2 = wS + 64;
    const float* w3 = wS + 128;
    float* const T1w = T1[w];
    float* const T2w = T2[w];

    // x into registers, then same 3-step pipeline
    float xv[24];
    #pragma unroll
    for (int m = 0; m < 3; ++m)
        #pragma unroll
        for (int i = 0; i < 8; ++i)
            xv[i * 3 + m] = xsw[i * 96 + lane + 32 * m];
    __syncwarp();

    #pragma unroll
    for (int a = 0; a < 8; ++a) {
        float wr[8];
        #pragma unroll
        for (int i = 0; i < 8; ++i) wr[i] = w1[a * 8 + i];
        #pragma unroll
        for (int m = 0; m < 3; ++m) {
            float acc = 0.f;
            #pragma unroll
            for (int i = 0; i < 8; ++i) acc += wr[i] * xv[i * 3 + m];
            T1w[a * TST + lane + 32 * m] = acc;
        }
    }
    __syncwarp();

    #pragma unroll
    for (int m = 0; m < 3; ++m) {
        const int r2 = lane + 32 * m;
        const int a2 = r2 / 12, k2 = r2 - a2 * 12;
        float tv[8];
        #pragma unroll
        for (int j = 0; j < 8; ++j) tv[j] = T1w[a2 * TST + j * 12 + k2];
        #pragma unroll
        for (int cc = 0; cc < 8; ++cc) {
            float acc = 0.f;
            #pragma unroll
            for (int j = 0; j < 8; ++j) acc += w2[cc * 8 + j] * tv[j];
            T2w[a2 * TST + cc * 12 + k2] = acc;
        }
    }
    __syncwarp();

    #pragma unroll
    for (int m = 0; m < 2; ++m) {
        const int r3 = lane + 32 * m;
        const int a3 = r3 >> 3, c3 = r3 & 7;
        float uv[12];
        #pragma unroll
        for (int k = 0; k < 12; ++k) uv[k] = T2w[a3 * TST + c3 * 12 + k];
        const float* bb = bo + a3 * 96 + c3 * 12;
        float res[12];
        #pragma unroll
        for (int d = 0; d < 12; ++d) {
            float acc = bb[d];
            #pragma unroll
            for (int k = 0; k < 12; ++k) acc += w3[d * 12 + k] * uv[k];
            res[d] = acc;
        }
        float4* op = (float4*)(out + (size_t)tok * C + a3 * 96 + c3 * 12);
        op[0] = make_float4(res[0], res[1], res[2],  res[3]);
        op[1] = make_float4(res[4], res[5], res[6],  res[7]);
        op[2] = make_float4(res[8], res[9], res[10], res[11]);
    }
}

// ---------------------------------------------------------------------------
// Launch
// ---------------------------------------------------------------------------
extern "C" void kernel_launch(void* const* d_in, const int* in_sizes, int n_in,
                              void* d_out, int out_size)
{
    const float* x   = (const float*)d_in[0];
    const float* wq1 = (const float*)d_in[1];
    const float* wq2 = (const float*)d_in[2];
    const float* wq3 = (const float*)d_in[3];
    const float* bq  = (const float*)d_in[4];
    const float* wk1 = (const float*)d_in[5];
    const float* wk2 = (const float*)d_in[6];
    const float* wk3 = (const float*)d_in[7];
    const float* bk  = (const float*)d_in[8];
    const float* wv1 = (const float*)d_in[9];
    const float* wv2 = (const float*)d_in[10];
    const float* wv3 = (const float*)d_in[11];
    const float* bv  = (const float*)d_in[12];
    const float* wo1 = (const float*)d_in[13];
    const float* wo2 = (const float*)d_in[14];
    const float* wo3 = (const float*)d_in[15];
    const float* bo  = (const float*)d_in[16];
    float* out = (float*)d_out;

    tle_qkv_kernel<<<NTOK / 4, 128>>>(x, wq1, wq2, wq3, bq,
                                         wk1, wk2, wk3, bk,
                                         wv1, wv2, wv3, bv);

    attn_kernel<<<dim3(5, NBH), 256>>>();

    tle_o_kernel<<<NTOK / 4, 128>>>(wo1, wo2, wo3, bo, out);
}